// round 1
// baseline (speedup 1.0000x reference)
#include <cuda_runtime.h>
#include <math.h>
#include <stdint.h>

// Problem dims
#define B_   2
#define S_   2048
#define D_   1024
#define H_   16
#define DK_  64
#define F_   4096
#define E_   8
#define TOK  (B_*S_)              // 4096 tokens
#define CAP_ROWS (TOK*2 + E_*128) // 9216 padded gather capacity

// GEMM tiling
#define BM 64
#define BN 64
#define BK 16

// ---------------- scratch (device globals; no allocation) ----------------
__device__ __align__(128) float g_x2[TOK*D_];
__device__ __align__(128) float g_q [TOK*D_];
__device__ __align__(128) float g_k [TOK*D_];
__device__ __align__(128) float g_v [TOK*D_];
__device__ __align__(128) float g_attn[TOK*D_];
__device__ __align__(128) float g_kvp[32*8*DK_*DK_];
__device__ __align__(128) float g_kv [32*DK_*DK_];
__device__ __align__(128) float g_ksp[32*8*DK_];
__device__ __align__(128) float g_ks [32*DK_];
__device__ __align__(128) float g_xg[(size_t)CAP_ROWS*D_];
__device__ __align__(128) float g_h [(size_t)CAP_ROWS*F_];
__device__ __align__(128) float g_y [(size_t)CAP_ROWS*D_];
__device__ int   g_cnt[E_];
__device__ int   g_off[E_+1];
__device__ int   g_cur[E_];
__device__ int   g_topi[TOK*2];
__device__ float g_topw[TOK*2];
__device__ int   g_row[TOK*2];

// ---------------- helpers ----------------
__device__ __forceinline__ float silu_gate(float a, float c) {
    return a / (1.f + expf(-a)) * c;
}
__device__ __forceinline__ float phi1(float x) {   // elu(x)+1
    return x > 0.f ? x + 1.f : expf(x);
}

#define FMA16(ACC, a, bv) do { \
    ACC[0][0] += a.x*bv.x; ACC[0][1] += a.x*bv.y; ACC[0][2] += a.x*bv.z; ACC[0][3] += a.x*bv.w; \
    ACC[1][0] += a.y*bv.x; ACC[1][1] += a.y*bv.y; ACC[1][2] += a.y*bv.z; ACC[1][3] += a.y*bv.w; \
    ACC[2][0] += a.z*bv.x; ACC[2][1] += a.z*bv.y; ACC[2][2] += a.z*bv.z; ACC[2][3] += a.z*bv.w; \
    ACC[3][0] += a.w*bv.x; ACC[3][1] += a.w*bv.y; ACC[3][2] += a.w*bv.z; ACC[3][3] += a.w*bv.w; \
} while (0)

// Shared GEMM tile loop. A: row-major [.. x lda], already offset to block row.
// W0/W1: row-major [K x ldw], already offset to block col. 256 threads.
template<int NW>
__device__ __forceinline__ void gemm_body(
    const float* __restrict__ A, int lda,
    const float* __restrict__ W0, const float* __restrict__ W1,
    int ldw, int K,
    float (&acc0)[4][4], float (&acc1)[4][4])
{
    __shared__ float As[BK*BM];
    __shared__ float Ws[NW][BK*BN];
    const int tid = threadIdx.x;
    const int tx = tid & 15, ty = tid >> 4;
    const int ar = tid >> 2;            // 0..63
    const int ac = (tid & 3) << 2;      // 0,4,8,12
    const int wr = tid >> 4;            // 0..15
    const int wc = (tid & 15) << 2;     // 0..60

    for (int k0 = 0; k0 < K; k0 += BK) {
        float4 av = *(const float4*)(A + (size_t)ar*lda + k0 + ac);
        As[(ac+0)*BM + ar] = av.x;
        As[(ac+1)*BM + ar] = av.y;
        As[(ac+2)*BM + ar] = av.z;
        As[(ac+3)*BM + ar] = av.w;
        *(float4*)(&Ws[0][wr*BN + wc]) = *(const float4*)(W0 + (size_t)(k0+wr)*ldw + wc);
        if (NW == 2)
            *(float4*)(&Ws[1][wr*BN + wc]) = *(const float4*)(W1 + (size_t)(k0+wr)*ldw + wc);
        __syncthreads();
        #pragma unroll
        for (int kk = 0; kk < BK; kk++) {
            float4 a  = *(const float4*)(&As[kk*BM + ty*4]);
            float4 b0 = *(const float4*)(&Ws[0][kk*BN + tx*4]);
            FMA16(acc0, a, b0);
            if (NW == 2) {
                float4 b1 = *(const float4*)(&Ws[1][kk*BN + tx*4]);
                FMA16(acc1, a, b1);
            }
        }
        __syncthreads();
    }
}

// ---------------- kernels ----------------

// LayerNorm over D, block per token, writes g_x2
__global__ void __launch_bounds__(256) ln_kernel(
    const float* __restrict__ x, const float* __restrict__ g, const float* __restrict__ b)
{
    __shared__ float rs[256], rq[256];
    const int t = blockIdx.x, tid = threadIdx.x;
    float4 v = ((const float4*)(x + (size_t)t*D_))[tid];
    rs[tid] = v.x + v.y + v.z + v.w;
    rq[tid] = v.x*v.x + v.y*v.y + v.z*v.z + v.w*v.w;
    __syncthreads();
    for (int o = 128; o > 0; o >>= 1) {
        if (tid < o) { rs[tid] += rs[tid+o]; rq[tid] += rq[tid+o]; }
        __syncthreads();
    }
    float mean = rs[0] * (1.f/D_);
    float var  = rq[0] * (1.f/D_) - mean*mean;
    float inv  = rsqrtf(var + 1e-5f);
    float4 gg = ((const float4*)g)[tid];
    float4 bb = ((const float4*)b)[tid];
    float4 o4;
    o4.x = (v.x - mean)*inv*gg.x + bb.x;
    o4.y = (v.y - mean)*inv*gg.y + bb.y;
    o4.z = (v.z - mean)*inv*gg.z + bb.z;
    o4.w = (v.w - mean)*inv*gg.w + bb.w;
    ((float4*)(g_x2 + (size_t)t*D_))[tid] = o4;
}

// Gated projection: C = maybe_phi( silu(x2@W1+b1) * (x2@W2+b2) ), dst: 0=q 1=k 2=v
__global__ void __launch_bounds__(256) gated_proj_kernel(
    const float* __restrict__ W1, const float* __restrict__ b1,
    const float* __restrict__ W2, const float* __restrict__ b2,
    int dst, int applyPhi)
{
    const int bm0 = blockIdx.x * BM, bn0 = blockIdx.y * BN;
    float acc0[4][4] = {}, acc1[4][4] = {};
    gemm_body<2>(g_x2 + (size_t)bm0*D_, D_, W1 + bn0, W2 + bn0, D_, D_, acc0, acc1);
    float* C = (dst == 0) ? g_q : (dst == 1) ? g_k : g_v;
    const int tx = threadIdx.x & 15, ty = threadIdx.x >> 4;
    const int n0 = bn0 + tx*4;
    float4 bb1 = *(const float4*)(b1 + n0);
    float4 bb2 = *(const float4*)(b2 + n0);
    #pragma unroll
    for (int i = 0; i < 4; i++) {
        int m = bm0 + ty*4 + i;
        float4 o;
        o.x = silu_gate(acc0[i][0] + bb1.x, acc1[i][0] + bb2.x);
        o.y = silu_gate(acc0[i][1] + bb1.y, acc1[i][1] + bb2.y);
        o.z = silu_gate(acc0[i][2] + bb1.z, acc1[i][2] + bb2.z);
        o.w = silu_gate(acc0[i][3] + bb1.w, acc1[i][3] + bb2.w);
        if (applyPhi) { o.x = phi1(o.x); o.y = phi1(o.y); o.z = phi1(o.z); o.w = phi1(o.w); }
        *(float4*)(C + (size_t)m*D_ + n0) = o;
    }
}

// Partial kv outer-product accumulation per (b,h,chunk of 256 s)
__global__ void __launch_bounds__(256) kv_partial_kernel()
{
    __shared__ float pk[DK_], pv[DK_];
    const int bh = blockIdx.x, c = blockIdx.y;
    const int b = bh >> 4, h = bh & 15;
    const int tid = threadIdx.x;
    const int d = tid >> 2, eg = tid & 3;
    float acc[16];
    #pragma unroll
    for (int j = 0; j < 16; j++) acc[j] = 0.f;
    float ks = 0.f;
    for (int s = c*256; s < c*256 + 256; s++) {
        size_t base = ((size_t)(b*S_ + s))*D_ + h*DK_;
        if (tid < 64)        pk[tid]      = g_k[base + tid];
        else if (tid < 128)  pv[tid - 64] = g_v[base + tid - 64];
        __syncthreads();
        float kd = pk[d];
        #pragma unroll
        for (int j = 0; j < 16; j++) acc[j] += kd * pv[eg + 4*j];
        if (eg == 0) ks += kd;
        __syncthreads();
    }
    size_t ob = ((size_t)(bh*8 + c))*DK_*DK_;
    #pragma unroll
    for (int j = 0; j < 16; j++) g_kvp[ob + d*DK_ + eg + 4*j] = acc[j];
    if (eg == 0) g_ksp[(bh*8 + c)*DK_ + d] = ks;
}

__global__ void kv_reduce_kernel()
{
    int i = blockIdx.x*256 + threadIdx.x;
    if (i < 32*DK_*DK_) {
        int bh = i >> 12, r = i & 4095;
        float s = 0.f;
        #pragma unroll
        for (int c = 0; c < 8; c++) s += g_kvp[((size_t)(bh*8 + c))*4096 + r];
        g_kv[i] = s;
    }
    int j = i - 32*DK_*DK_;
    if (j >= 0 && j < 32*DK_) {
        int bh = j >> 6, d = j & 63;
        float s = 0.f;
        #pragma unroll
        for (int c = 0; c < 8; c++) s += g_ksp[(bh*8 + c)*DK_ + d];
        g_ks[j] = s;
    }
}

// num/den: out = (phi_q @ kv) / (phi_q . ksum + eps)
__global__ void __launch_bounds__(256) attn_apply_kernel()
{
    __shared__ float kvs[DK_*DK_];
    __shared__ float kss[DK_];
    __shared__ float qs[4*DK_];
    const int bh = blockIdx.x;
    const int b = bh >> 4, h = bh & 15;
    const int tid = threadIdx.x;
    for (int i = tid; i < DK_*DK_; i += 256) kvs[i] = g_kv[(size_t)bh*DK_*DK_ + i];
    if (tid < DK_) kss[tid] = g_ks[bh*DK_ + tid];
    __syncthreads();
    const int sl = tid >> 6, e = tid & 63;
    const int sbase = blockIdx.y * 64;
    for (int pass = 0; pass < 16; pass++) {
        int s = sbase + pass*4 + sl;
        qs[tid] = g_q[((size_t)(b*S_ + s))*D_ + h*DK_ + e];
        __syncthreads();
        float acc = 0.f, qk = 0.f;
        #pragma unroll
        for (int d = 0; d < DK_; d++) {
            float qd = qs[sl*DK_ + d];
            acc += qd * kvs[d*DK_ + e];
            qk  += qd * kss[d];
        }
        g_attn[((size_t)(b*S_ + s))*D_ + h*DK_ + e] = acc / (qk + 1e-6f);
        __syncthreads();
    }
}

// out = attn @ wo + bo + residual x  (writes full d_out)
__global__ void __launch_bounds__(256) out_proj_kernel(
    const float* __restrict__ W, const float* __restrict__ bias,
    const float* __restrict__ res, float* __restrict__ C)
{
    const int bm0 = blockIdx.x * BM, bn0 = blockIdx.y * BN;
    float acc0[4][4] = {}, accd[4][4] = {};
    gemm_body<1>(g_attn + (size_t)bm0*D_, D_, W + bn0, (const float*)0, D_, D_, acc0, accd);
    const int tx = threadIdx.x & 15, ty = threadIdx.x >> 4;
    const int n0 = bn0 + tx*4;
    float4 bb = *(const float4*)(bias + n0);
    #pragma unroll
    for (int i = 0; i < 4; i++) {
        int m = bm0 + ty*4 + i;
        float4 rr = *(const float4*)(res + (size_t)m*D_ + n0);
        float4 o;
        o.x = acc0[i][0] + bb.x + rr.x;
        o.y = acc0[i][1] + bb.y + rr.y;
        o.z = acc0[i][2] + bb.z + rr.z;
        o.w = acc0[i][3] + bb.w + rr.w;
        *(float4*)(C + (size_t)m*D_ + n0) = o;
    }
}

__global__ void zero_cnt_kernel() { if (threadIdx.x < E_) g_cnt[threadIdx.x] = 0; }

__global__ void zero_xg_kernel()
{
    size_t i = ((size_t)blockIdx.x*256 + threadIdx.x)*4;
    *(float4*)(g_xg + i) = make_float4(0.f, 0.f, 0.f, 0.f);
}

// gate logits + softmax + top2 ; one warp per token
__global__ void __launch_bounds__(256) routing_kernel(
    const float* __restrict__ gw, const float* __restrict__ gb)
{
    const int lane = threadIdx.x & 31;
    const int warp = threadIdx.x >> 5;
    const int t = blockIdx.x*8 + warp;
    const float* xr = g_x2 + (size_t)t*D_;
    float lg[8];
    #pragma unroll
    for (int e = 0; e < 8; e++) lg[e] = 0.f;
    for (int d = lane; d < D_; d += 32) {
        float xv = xr[d];
        const float4* wr = (const float4*)(gw + (size_t)d*8);
        float4 w0 = wr[0], w1 = wr[1];
        lg[0] += xv*w0.x; lg[1] += xv*w0.y; lg[2] += xv*w0.z; lg[3] += xv*w0.w;
        lg[4] += xv*w1.x; lg[5] += xv*w1.y; lg[6] += xv*w1.z; lg[7] += xv*w1.w;
    }
    #pragma unroll
    for (int o = 16; o > 0; o >>= 1) {
        #pragma unroll
        for (int e = 0; e < 8; e++) lg[e] += __shfl_xor_sync(0xffffffffu, lg[e], o);
    }
    if (lane == 0) {
        float p[8], mx = -1e30f;
        #pragma unroll
        for (int e = 0; e < 8; e++) { lg[e] += gb[e]; mx = fmaxf(mx, lg[e]); }
        float se = 0.f;
        #pragma unroll
        for (int e = 0; e < 8; e++) { p[e] = expf(lg[e] - mx); se += p[e]; }
        int i0 = 0;
        #pragma unroll
        for (int e = 1; e < 8; e++) if (p[e] > p[i0]) i0 = e;
        int i1 = (i0 == 0) ? 1 : 0;
        #pragma unroll
        for (int e = 0; e < 8; e++) if (e != i0 && p[e] > p[i1]) i1 = e;
        float v0 = p[i0]/se, v1 = p[i1]/se;
        float inv = 1.f / (v0 + v1 + 1e-6f);
        g_topi[t*2]   = i0; g_topi[t*2+1] = i1;
        g_topw[t*2]   = v0*inv; g_topw[t*2+1] = v1*inv;
        atomicAdd(&g_cnt[i0], 1);
        atomicAdd(&g_cnt[i1], 1);
    }
}

__global__ void offsets_kernel()
{
    if (threadIdx.x == 0) {
        int o = 0;
        for (int e = 0; e < E_; e++) {
            g_off[e] = o;
            o += (g_cnt[e] + 127) & ~127;
            g_cur[e] = 0;
        }
        g_off[E_] = o;
    }
}

// assign a row per (token,slot) and copy x2 row into gather buffer
__global__ void __launch_bounds__(256) place_gather_kernel()
{
    const int slot = blockIdx.x;
    const int t = slot >> 1;
    __shared__ int row_s;
    if (threadIdx.x == 0) {
        int e = g_topi[slot];
        int pos = atomicAdd(&g_cur[e], 1);
        int row = g_off[e] + pos;
        g_row[slot] = row;
        row_s = row;
    }
    __syncthreads();
    int row = row_s;
    float4* dst = (float4*)(g_xg + (size_t)row*D_);
    const float4* src = (const float4*)(g_x2 + (size_t)t*D_);
    dst[threadIdx.x] = src[threadIdx.x];
}

// h = silu(xg@w1[e]+b1[e]) * (xg@w3[e]+b3[e])
__global__ void __launch_bounds__(256) moe_h_kernel(
    const float* __restrict__ ew1, const float* __restrict__ eb1,
    const float* __restrict__ ew3, const float* __restrict__ eb3)
{
    const int bm0 = blockIdx.x * BM;
    if (bm0 >= g_off[E_]) return;
    int e = 0;
    #pragma unroll
    for (int i = 0; i < E_; i++) if (bm0 >= g_off[i+1]) e = i + 1;
    const int bn0 = blockIdx.y * BN;
    float acc0[4][4] = {}, acc1[4][4] = {};
    gemm_body<2>(g_xg + (size_t)bm0*D_, D_,
                 ew1 + (size_t)e*D_*F_ + bn0,
                 ew3 + (size_t)e*D_*F_ + bn0, F_, D_, acc0, acc1);
    const int tx = threadIdx.x & 15, ty = threadIdx.x >> 4;
    const int n0 = bn0 + tx*4;
    float4 bb1 = *(const float4*)(eb1 + (size_t)e*F_ + n0);
    float4 bb3 = *(const float4*)(eb3 + (size_t)e*F_ + n0);
    #pragma unroll
    for (int i = 0; i < 4; i++) {
        int m = bm0 + ty*4 + i;
        float4 o;
        o.x = silu_gate(acc0[i][0] + bb1.x, acc1[i][0] + bb3.x);
        o.y = silu_gate(acc0[i][1] + bb1.y, acc1[i][1] + bb3.y);
        o.z = silu_gate(acc0[i][2] + bb1.z, acc1[i][2] + bb3.z);
        o.w = silu_gate(acc0[i][3] + bb1.w, acc1[i][3] + bb3.w);
        *(float4*)(g_h + (size_t)m*F_ + n0) = o;
    }
}

// y = h @ w2[e] + b2[e]
__global__ void __launch_bounds__(256) moe_y_kernel(
    const float* __restrict__ ew2, const float* __restrict__ eb2)
{
    const int bm0 = blockIdx.x * BM;
    if (bm0 >= g_off[E_]) return;
    int e = 0;
    #pragma unroll
    for (int i = 0; i < E_; i++) if (bm0 >= g_off[i+1]) e = i + 1;
    const int bn0 = blockIdx.y * BN;
    float acc0[4][4] = {}, accd[4][4] = {};
    gemm_body<1>(g_h + (size_t)bm0*F_, F_,
                 ew2 + (size_t)e*F_*D_ + bn0, (const float*)0, D_, F_, acc0, accd);
    const int tx = threadIdx.x & 15, ty = threadIdx.x >> 4;
    const int n0 = bn0 + tx*4;
    float4 bb = *(const float4*)(eb2 + (size_t)e*D_ + n0);
    #pragma unroll
    for (int i = 0; i < 4; i++) {
        int m = bm0 + ty*4 + i;
        float4 o;
        o.x = acc0[i][0] + bb.x;
        o.y = acc0[i][1] + bb.y;
        o.z = acc0[i][2] + bb.z;
        o.w = acc0[i][3] + bb.w;
        *(float4*)(g_y + (size_t)m*D_ + n0) = o;
    }
}

// out[t] += w0*y[row0] + w1*y[row1]
__global__ void __launch_bounds__(256) combine_kernel(float* __restrict__ out)
{
    const int t = blockIdx.x;
    const int r0 = g_row[2*t], r1 = g_row[2*t+1];
    const float w0 = g_topw[2*t], w1 = g_topw[2*t+1];
    const int c = threadIdx.x;
    float4 o  = ((float4*)(out + (size_t)t*D_))[c];
    float4 y0 = ((const float4*)(g_y + (size_t)r0*D_))[c];
    float4 y1 = ((const float4*)(g_y + (size_t)r1*D_))[c];
    o.x += w0*y0.x + w1*y1.x;
    o.y += w0*y0.y + w1*y1.y;
    o.z += w0*y0.z + w1*y1.z;
    o.w += w0*y0.w + w1*y1.w;
    ((float4*)(out + (size_t)t*D_))[c] = o;
}

// ---------------- launch ----------------
extern "C" void kernel_launch(void* const* d_in, const int* in_sizes, int n_in,
                              void* d_out, int out_size)
{
    const float* x    = (const float*)d_in[0];
    const float* wq1  = (const float*)d_in[1];
    const float* bq1  = (const float*)d_in[2];
    const float* wq2  = (const float*)d_in[3];
    const float* bq2  = (const float*)d_in[4];
    const float* wk1  = (const float*)d_in[5];
    const float* bk1  = (const float*)d_in[6];
    const float* wk2  = (const float*)d_in[7];
    const float* bk2  = (const float*)d_in[8];
    const float* wv1  = (const float*)d_in[9];
    const float* bv1  = (const float*)d_in[10];
    const float* wv2  = (const float*)d_in[11];
    const float* bv2  = (const float*)d_in[12];
    const float* wo   = (const float*)d_in[13];
    const float* bo   = (const float*)d_in[14];
    const float* ln1g = (const float*)d_in[15];
    const float* ln1b = (const float*)d_in[16];
    const float* ln2g = (const float*)d_in[17];
    const float* ln2b = (const float*)d_in[18];
    const float* gw   = (const float*)d_in[19];
    const float* gb   = (const float*)d_in[20];
    const float* ew1  = (const float*)d_in[21];
    const float* eb1  = (const float*)d_in[22];
    const float* ew2  = (const float*)d_in[23];
    const float* eb2  = (const float*)d_in[24];
    const float* ew3  = (const float*)d_in[25];
    const float* eb3  = (const float*)d_in[26];
    float* out = (float*)d_out;

    dim3 gDD(TOK/BM, D_/BN);   // 64 x 16

    // x2 = LN1(x)
    ln_kernel<<<TOK, 256>>>(x, ln1g, ln1b);
    // q,k,v gated projections (phi on q,k)
    gated_proj_kernel<<<gDD, 256>>>(wq1, bq1, wq2, bq2, 0, 1);
    gated_proj_kernel<<<gDD, 256>>>(wk1, bk1, wk2, bk2, 1, 1);
    gated_proj_kernel<<<gDD, 256>>>(wv1, bv1, wv2, bv2, 2, 0);
    // linear attention
    kv_partial_kernel<<<dim3(32, 8), 256>>>();
    kv_reduce_kernel<<<(32*DK_*DK_ + 32*DK_ + 255)/256, 256>>>();
    attn_apply_kernel<<<dim3(32, S_/64), 256>>>();
    // out = attn@wo + bo + x
    out_proj_kernel<<<gDD, 256>>>(wo, bo, x, out);
    // x2 = LN2(out)
    ln_kernel<<<TOK, 256>>>(out, ln2g, ln2b);
    // MoE routing
    zero_cnt_kernel<<<1, 32>>>();
    routing_kernel<<<TOK/8, 256>>>(gw, gb);
    offsets_kernel<<<1, 1>>>();
    zero_xg_kernel<<<CAP_ROWS*D_/1024, 256>>>();
    place_gather_kernel<<<TOK*2, 256>>>();
    // expert GEMMs on gathered rows
    moe_h_kernel<<<dim3(CAP_ROWS/BM, F_/BN), 256>>>(ew1, eb1, ew3, eb3);
    moe_y_kernel<<<dim3(CAP_ROWS/BM, D_/BN), 256>>>(ew2, eb2);
    // scatter-combine into residual
    combine_kernel<<<TOK, 256>>>(out);
}